// round 14
// baseline (speedup 1.0000x reference)
#include <cuda_runtime.h>
#include <cuda_bf16.h>
#include <cuda_fp16.h>
#include <math.h>
#include <stdint.h>

#define C 128
#define MIXD 640
#define E_MAX 100000
#define N_MAX 10000

typedef unsigned long long u64;

// ---------------- scratch (static device arrays: allocation-free) ----------
__device__ __align__(16) __half g_mix[(size_t)E_MAX * MIXD];      // slot-ordered
__device__ __align__(16) float  g_geo[(size_t)(E_MAX + 256) * 12]; // slot-ordered
__device__ __align__(16) __half g_w3t[MIXD * 64];   // w3^T/8 fp16
__device__ __align__(16) __half g_w1t[64 * 64];     // w1^T/8 fp16
__device__ __align__(16) __half g_w2t[64 * 64];     // w2^T/8 fp16
__device__ int g_cnt[N_MAX];
__device__ int g_cur[N_MAX];
__device__ int g_off[N_MAX + 1];
__device__ int g_perm[E_MAX];      // slot -> edge id
__device__ int g_psdr[E_MAX];      // slot -> sender node

// ---------------- f32x2 helpers --------------------------------------------
__device__ __forceinline__ u64 pk2(float x) {
    u64 r; asm("mov.b64 %0,{%1,%1};" : "=l"(r) : "f"(x)); return r;
}
__device__ __forceinline__ void fma2(u64& d, u64 a, u64 b) {
    asm("fma.rn.f32x2 %0, %1, %2, %0;" : "+l"(d) : "l"(a), "l"(b));
}
__device__ __forceinline__ float2 upk(u64 v) {
    float2 r; asm("mov.b64 {%0,%1}, %2;" : "=f"(r.x), "=f"(r.y) : "l"(v)); return r;
}
__device__ __forceinline__ float siluf(float x) { return x / (1.0f + expf(-x)); }

// layer0 (KD=8), writing silu result as fp16 directly into the SMEM A row
__device__ __forceinline__ void dense64_h0(const float* __restrict__ W,
                                           const float* in, char* rowp,
                                           float scale) {
#pragma unroll
    for (int t = 0; t < 2; t++) {
        u64 acc[16];
#pragma unroll
        for (int i = 0; i < 16; i++) acc[i] = 0ull;
#pragma unroll
        for (int k = 0; k < 8; k++) {
            u64 hk = pk2(in[k]);
            const ulonglong2* w = (const ulonglong2*)(W + k * 64 + t * 32);
#pragma unroll
            for (int p = 0; p < 8; p++) {
                ulonglong2 u = w[p];
                fma2(acc[2 * p], u.x, hk);
                fma2(acc[2 * p + 1], u.y, hk);
            }
        }
#pragma unroll
        for (int i = 0; i < 16; i++) {
            float2 f = upk(acc[i]);
            __half2 p = __floats2half2_rn(siluf(f.x * scale), siluf(f.y * scale));
            *(uint32_t*)(rowp + t * 64 + i * 4) = *(uint32_t*)&p;
        }
    }
}

// ---------------- mma / ldmatrix helpers ------------------------------------
__device__ __forceinline__ uint32_t smem_u32(const void* p) {
    uint32_t a;
    asm("{ .reg .u64 t; cvta.to.shared.u64 t, %1; cvt.u32.u64 %0, t; }"
        : "=r"(a) : "l"(p));
    return a;
}
__device__ __forceinline__ void ldm_x4(uint32_t* r, uint32_t addr) {
    asm volatile("ldmatrix.sync.aligned.m8n8.x4.shared.b16 {%0,%1,%2,%3}, [%4];"
                 : "=r"(r[0]), "=r"(r[1]), "=r"(r[2]), "=r"(r[3]) : "r"(addr));
}
__device__ __forceinline__ void mma_f16(float* d, const uint32_t* a,
                                        const uint32_t* b) {
    asm volatile(
        "mma.sync.aligned.m16n8k16.row.col.f32.f16.f16.f32 "
        "{%0,%1,%2,%3}, {%4,%5,%6,%7}, {%8,%9}, {%0,%1,%2,%3};"
        : "+f"(d[0]), "+f"(d[1]), "+f"(d[2]), "+f"(d[3])
        : "r"(a[0]), "r"(a[1]), "r"(a[2]), "r"(a[3]), "r"(b[0]), "r"(b[1]));
}

// ---------------- prep: zero out + counters + weight transposes -------------
__global__ void k_prep(const float* __restrict__ w1, const float* __restrict__ w2,
                       const float* __restrict__ w3, float* __restrict__ out,
                       int N) {
    int i = blockIdx.x * blockDim.x + threadIdx.x;
    if (i < MIXD * 64) {
        int n = i >> 6, k = i & 63;
        g_w3t[i] = __float2half_rn(w3[k * MIXD + n] * 0.125f);
    }
    if (i < 64 * 64) {
        int n = i >> 6, k = i & 63;
        g_w1t[i] = __float2half_rn(w1[k * 64 + n] * 0.125f);
        g_w2t[i] = __float2half_rn(w2[k * 64 + n] * 0.125f);
    }
    if (i < N) { g_cnt[i] = 0; g_cur[i] = 0; }
    int total4 = (N * 1408) >> 2;
    float4 z = {0.f, 0.f, 0.f, 0.f};
    for (int j = i; j < total4; j += gridDim.x * blockDim.x)
        ((float4*)out)[j] = z;
}
__global__ void k_hist(const int* __restrict__ recv, int E) {
    int i = blockIdx.x * blockDim.x + threadIdx.x;
    if (i < E) atomicAdd(&g_cnt[recv[i]], 1);
}
__global__ void k_scan(int N) {
    __shared__ int wsum[32];
    int tid = threadIdx.x, lane = tid & 31, wid = tid >> 5;
    int per = (N + 1023) >> 10;
    int st = tid * per, en = min(st + per, N);
    int s = 0;
    for (int i = st; i < en; i++) s += g_cnt[i];
    int v = s;
#pragma unroll
    for (int o = 1; o < 32; o <<= 1) {
        int u = __shfl_up_sync(0xffffffffu, v, o);
        if (lane >= o) v += u;
    }
    if (lane == 31) wsum[wid] = v;
    __syncthreads();
    if (wid == 0) {
        int w = wsum[lane];
#pragma unroll
        for (int o = 1; o < 32; o <<= 1) {
            int u = __shfl_up_sync(0xffffffffu, w, o);
            if (lane >= o) w += u;
        }
        wsum[lane] = w;
    }
    __syncthreads();
    int base = (wid > 0 ? wsum[wid - 1] : 0) + (v - s);
    int run = base;
    for (int i = st; i < en; i++) { g_off[i] = run; run += g_cnt[i]; }
    if (tid == 1023) g_off[N] = run;
}
__global__ void k_scatter(const int* __restrict__ recv,
                          const int* __restrict__ snd, int E) {
    int i = blockIdx.x * blockDim.x + threadIdx.x;
    if (i < E) {
        int r = recv[i];
        int p = atomicAdd(&g_cur[r], 1);
        int slot = g_off[r] + p;
        g_perm[slot] = i;
        g_psdr[slot] = snd[i];
    }
}

// ---------------- k_edge: layer0 + layers1-2 + w3 GEMM, fused (slot order) --
// SMEM: A 256x144 = 36864 | W 80x144 = 11520 | stage 128x176 = 22528
#define E_A 0
#define E_W 36864
#define E_S 48384
#define E_TOTAL 70912

__global__ void __launch_bounds__(256, 3) k_edge(
    const float* __restrict__ vectors, const float* __restrict__ radial,
    const float* __restrict__ w0, int E) {
    extern __shared__ char sm[];
    int tid = threadIdx.x;
    int w = tid >> 5, lane = tid & 31;
    int e0 = blockIdx.x * 256;
    int g = lane >> 3, r8 = lane & 7;
    int m_lane = lane >> 2, n_lane = (lane & 3) * 2;

    // ---- phase 0: geometry + layer0 -> SMEM A rows (slot-ordered inputs) ----
    {
        float* w0s = (float*)(sm + E_S);
        float4* d = (float4*)w0s; const float4* s4 = (const float4*)w0;
        for (int i = tid; i < 128; i += 256) d[i] = s4[i];

        int p = e0 + tid;
        int pc = min(p, E - 1);
        bool valid = (p < E);
        int e = g_perm[pc];
        {
            float x = vectors[(size_t)e * 3 + 0];
            float y = vectors[(size_t)e * 3 + 1];
            float z = vectors[(size_t)e * 3 + 2];
            float inv = rsqrtf(x * x + y * y + z * z);
            float r0 = x * inv, r1 = y * inv, r2 = z * inv;
            const float SQ3 = 1.7320508075688772f;
            if (valid) {
                float* G = g_geo + (size_t)p * 12;
                G[0] = r0; G[1] = r1; G[2] = r2;
                G[3] = SQ3 * (r0 * r0 - (1.f / 3.f));
                G[4] = SQ3 * r0 * r1;
                G[5] = SQ3 * r0 * r2;
                G[6] = SQ3 * r1 * r0;
                G[7] = SQ3 * (r1 * r1 - (1.f / 3.f));
                G[8] = SQ3 * r1 * r2;
                G[9] = SQ3 * r2 * r0;
                G[10] = SQ3 * r2 * r1;
                G[11] = SQ3 * (r2 * r2 - (1.f / 3.f));
            }
        }
        float rin[8];
        {
            const float4* rp = (const float4*)(radial + (size_t)e * 8);
            float4 a4 = rp[0], b4 = rp[1];
            rin[0] = a4.x; rin[1] = a4.y; rin[2] = a4.z; rin[3] = a4.w;
            rin[4] = b4.x; rin[5] = b4.y; rin[6] = b4.z; rin[7] = b4.w;
        }
        __syncthreads();  // w0s ready
        dense64_h0(w0s, rin, sm + E_A + tid * 144, 0.35355339059327373f);
    }

    uint32_t Ab = smem_u32(sm + E_A);
    uint32_t Wb = smem_u32(sm + E_W);

    // ---- phases 1-2: layers 1-2, in-place on SMEM A ----
#pragma unroll
    for (int L = 0; L < 2; L++) {
        const __half* wt = (L == 0) ? g_w1t : g_w2t;
        __syncthreads();
        for (int idx = tid; idx < 512; idx += 256) {
            int row = idx >> 3, seg = idx & 7;
            *(uint4*)(sm + E_W + row * 144 + seg * 16) =
                ((const uint4*)(wt + (size_t)row * 64))[seg];
        }
        __syncthreads();

#pragma unroll
        for (int mt = 0; mt < 2; mt++) {
            int rbase = 32 * w + 16 * mt;
            uint32_t aF[4][4];
#pragma unroll
            for (int kt = 0; kt < 4; kt++) {
                uint32_t off = (uint32_t)(rbase + (g & 1) * 8 + r8) * 144 +
                               kt * 32 + (g >> 1) * 16;
                ldm_x4(aF[kt], Ab + off);
            }
            uint32_t o[8][2];
#pragma unroll
            for (int nt = 0; nt < 8; nt++) {
                uint32_t bF[8];
#pragma unroll
                for (int p = 0; p < 2; p++) {
                    uint32_t off = (uint32_t)(nt * 8 + r8) * 144 + p * 64 + g * 16;
                    ldm_x4(&bF[p * 4], Wb + off);
                }
                float acc[4] = {0.f, 0.f, 0.f, 0.f};
#pragma unroll
                for (int kt = 0; kt < 4; kt++)
                    mma_f16(acc, aF[kt], &bF[kt * 2]);
#pragma unroll
                for (int half = 0; half < 2; half++) {
                    __half2 p = __floats2half2_rn(siluf(acc[half * 2]),
                                                  siluf(acc[half * 2 + 1]));
                    o[nt][half] = *(uint32_t*)&p;
                }
            }
#pragma unroll
            for (int nt = 0; nt < 8; nt++) {
                int col = nt * 8 + n_lane;
#pragma unroll
                for (int half = 0; half < 2; half++) {
                    int row = rbase + m_lane + half * 8;
                    *(uint32_t*)(sm + E_A + row * 144 + col * 2) = o[nt][half];
                }
            }
        }
    }
    __syncthreads();  // h2 rows visible

    // ---- phase 3: mix = h2 @ w3^T, stage -> g_mix (slot-ordered) ----
    uint32_t aF[2][4][4];
#pragma unroll
    for (int mt = 0; mt < 2; mt++) {
        int row = 32 * w + 16 * mt + (g & 1) * 8 + r8;
#pragma unroll
        for (int kt = 0; kt < 4; kt++)
            ldm_x4(aF[mt][kt], Ab + (uint32_t)row * 144 + kt * 32 + (g >> 1) * 16);
    }

    for (int cc = 0; cc < 8; cc++) {
        __syncthreads();
        for (int idx = tid; idx < 640; idx += 256) {
            int rown = idx >> 3, seg = idx & 7;
            *(uint4*)(sm + E_W + rown * 144 + seg * 16) =
                *((const uint4*)(g_w3t + (size_t)(cc * 80 + rown) * 64) + seg);
        }
        __syncthreads();

#pragma unroll
        for (int mt = 0; mt < 2; mt++) {
#pragma unroll
            for (int nt = 0; nt < 10; nt++) {
                uint32_t bF[8];
#pragma unroll
                for (int p = 0; p < 2; p++)
                    ldm_x4(&bF[p * 4],
                           Wb + (uint32_t)(nt * 8 + r8) * 144 + p * 64 + g * 16);
                float acc[4] = {0.f, 0.f, 0.f, 0.f};
#pragma unroll
                for (int kt = 0; kt < 4; kt++)
                    mma_f16(acc, aF[mt][kt], &bF[kt * 2]);
                int srow = w * 16 + m_lane;
                int cb = (nt * 8 + n_lane) * 2;
                *(__half2*)(sm + E_S + srow * 176 + cb) =
                    __floats2half2_rn(acc[0], acc[1]);
                *(__half2*)(sm + E_S + (srow + 8) * 176 + cb) =
                    __floats2half2_rn(acc[2], acc[3]);
            }
            __syncthreads();
            for (int idx = tid; idx < 2048; idx += 256) {
                int srow = idx >> 4, seg = idx & 15;
                int grow = e0 + 32 * (srow >> 4) + 16 * mt + (srow & 15);
                if (seg < 10 && grow < E)
                    *(uint4*)(g_mix + (size_t)grow * MIXD + cc * 80 + seg * 8) =
                        *(uint4*)(sm + E_S + srow * 176 + seg * 16);
            }
            __syncthreads();
        }
    }
}

// ---------------- k_node: slot-streaming consumer (zero smem) ---------------
__global__ void __launch_bounds__(128) k_node(
    const float* __restrict__ nf, float* __restrict__ out, int E, int N) {
    int c = threadIdx.x;
    int hs = blockIdx.x * 128;
    int he = min(hs + 128, E);
    if (hs >= E) return;

    // binary search: node with off[node] <= hs < off[node+1]
    int lo = 0, hi = N;
    while (lo < hi) {
        int mid = (lo + hi) >> 1;
        if (g_off[mid + 1] <= hs) lo = mid + 1; else hi = mid;
    }
    int node = lo;
    int nend = g_off[node + 1];

    float as0 = 0.f, as1 = 0.f;
    float av0 = 0.f, av1 = 0.f, av2 = 0.f;
    float aw0 = 0.f, aw1 = 0.f, aw2 = 0.f;
    float au0 = 0.f, au1 = 0.f, au2 = 0.f;
    const float sc = 0.31622776601683794f;  // 1/sqrt(10)

#define FLUSH(n)                                                            \
    do {                                                                    \
        float* ob = out + (size_t)(n) * 1408;                               \
        bool excl = (g_off[(n)] >= hs) && (g_off[(n) + 1] <= he);           \
        if (excl) {                                                         \
            ob[c] = as0 * sc;               ob[128 + c] = as1 * sc;         \
            ob[256 + 3 * c + 0] = av0 * sc; ob[256 + 3 * c + 1] = av1 * sc; \
            ob[256 + 3 * c + 2] = av2 * sc;                                 \
            ob[640 + 3 * c + 0] = aw0 * sc; ob[640 + 3 * c + 1] = aw1 * sc; \
            ob[640 + 3 * c + 2] = aw2 * sc;                                 \
            ob[1024 + 3 * c + 0] = au0 * sc;                                \
            ob[1024 + 3 * c + 1] = au1 * sc;                                \
            ob[1024 + 3 * c + 2] = au2 * sc;                                \
        } else {                                                            \
            atomicAdd(&ob[c], as0 * sc);                                    \
            atomicAdd(&ob[128 + c], as1 * sc);                              \
            atomicAdd(&ob[256 + 3 * c + 0], av0 * sc);                      \
            atomicAdd(&ob[256 + 3 * c + 1], av1 * sc);                      \
            atomicAdd(&ob[256 + 3 * c + 2], av2 * sc);                      \
            atomicAdd(&ob[640 + 3 * c + 0], aw0 * sc);                      \
            atomicAdd(&ob[640 + 3 * c + 1], aw1 * sc);                      \
            atomicAdd(&ob[640 + 3 * c + 2], aw2 * sc);                      \
            atomicAdd(&ob[1024 + 3 * c + 0], au0 * sc);                     \
            atomicAdd(&ob[1024 + 3 * c + 1], au1 * sc);                     \
            atomicAdd(&ob[1024 + 3 * c + 2], au2 * sc);                     \
        }                                                                   \
        as0 = as1 = av0 = av1 = av2 = 0.f;                                  \
        aw0 = aw1 = aw2 = au0 = au1 = au2 = 0.f;                            \
    } while (0)

    for (int gp = hs; gp < he; gp++) {
        while (gp >= nend) {
            FLUSH(node);
            node++;
            nend = g_off[node + 1];
        }
        int s = g_psdr[gp];
        const float* fr = nf + (size_t)s * 512;
        float ss = fr[c];
        float v0 = fr[128 + 3 * c + 0];
        float v1 = fr[128 + 3 * c + 1];
        float v2 = fr[128 + 3 * c + 2];
        const float4* G = (const float4*)(g_geo + (size_t)gp * 12);
        float4 ga = G[0], gb = G[1], gc4 = G[2];
        const __half* mx = g_mix + (size_t)gp * MIXD;
        float m0 = __half2float(mx[c]);
        float m1 = __half2float(mx[C + c]);
        float m2 = __half2float(mx[2 * C + c]);
        float m3 = __half2float(mx[3 * C + c]);
        float m4 = __half2float(mx[4 * C + c]);
        float r0 = ga.x, r1 = ga.y, r2 = ga.z;
        float y00 = ga.w, y01 = gb.x, y02 = gb.y, y11 = gb.w,
              y12 = gc4.x, y22 = gc4.w;
        float tp0 = v0 * r0 + v1 * r1 + v2 * r2;
        as0 += ss * m0;
        as1 += tp0 * m1;
        av0 += v0 * m2; av1 += v1 * m2; av2 += v2 * m2;
        float sm3 = ss * m3;
        aw0 += sm3 * r0; aw1 += sm3 * r1; aw2 += sm3 * r2;
        float t0 = y00 * v0 + y01 * v1 + y02 * v2;
        float t1 = y01 * v0 + y11 * v1 + y12 * v2;
        float t2 = y02 * v0 + y12 * v1 + y22 * v2;
        au0 += t0 * m4; au1 += t1 * m4; au2 += t2 * m4;
    }
    FLUSH(node);
#undef FLUSH
}

// ---------------- launch -----------------------------------------------------
extern "C" void kernel_launch(void* const* d_in, const int* in_sizes, int n_in,
                              void* d_out, int out_size) {
    const float* vectors    = (const float*)d_in[0];
    const float* node_feats = (const float*)d_in[1];
    const float* radial     = (const float*)d_in[2];
    const float* w0         = (const float*)d_in[3];
    const float* w1         = (const float*)d_in[4];
    const float* w2         = (const float*)d_in[5];
    const float* w3         = (const float*)d_in[6];
    const int*   senders    = (const int*)d_in[7];
    const int*   receivers  = (const int*)d_in[8];
    float* out = (float*)d_out;

    int E = in_sizes[0] / 3;
    int N = in_sizes[1] / 512;

    cudaFuncSetAttribute(k_edge, cudaFuncAttributeMaxDynamicSharedMemorySize,
                         E_TOTAL);

    k_prep<<<640, 256>>>(w1, w2, w3, out, N);
    k_hist<<<(E + 255) / 256, 256>>>(receivers, E);
    k_scan<<<1, 1024>>>(N);
    k_scatter<<<(E + 255) / 256, 256>>>(receivers, senders, E);
    k_edge<<<(E + 255) / 256, 256, E_TOTAL>>>(vectors, radial, w0, E);
    k_node<<<(E + 127) / 128, 128>>>(node_feats, out, E, N);
}

// round 15
// speedup vs baseline: 1.1837x; 1.1837x over previous
#include <cuda_runtime.h>
#include <cuda_bf16.h>
#include <cuda_fp16.h>
#include <math.h>
#include <stdint.h>

#define C 128
#define MIXD 640
#define E_MAX 100000
#define N_MAX 10000

typedef unsigned long long u64;

// ---------------- scratch (static device arrays: allocation-free) ----------
__device__ __align__(16) __half g_mix[(size_t)E_MAX * MIXD];
__device__ __align__(16) __half g_h[(size_t)(E_MAX + 256) * 64];  // h0 -> h2 in place
__device__ __align__(16) float  g_geo[(size_t)(E_MAX + 256) * 12];
__device__ __align__(16) __half g_w3t[MIXD * 64];   // w3^T/8 fp16
__device__ __align__(16) __half g_w1t[64 * 64];     // w1^T/8 fp16
__device__ __align__(16) __half g_w2t[64 * 64];     // w2^T/8 fp16
__device__ int g_cnt[N_MAX];
__device__ int g_cur[N_MAX];
__device__ int g_off[N_MAX + 1];
__device__ int g_csr[E_MAX];

// ---------------- f32x2 helpers --------------------------------------------
__device__ __forceinline__ u64 pk2(float x) {
    u64 r; asm("mov.b64 %0,{%1,%1};" : "=l"(r) : "f"(x)); return r;
}
__device__ __forceinline__ void fma2(u64& d, u64 a, u64 b) {
    asm("fma.rn.f32x2 %0, %1, %2, %0;" : "+l"(d) : "l"(a), "l"(b));
}
__device__ __forceinline__ float2 upk(u64 v) {
    float2 r; asm("mov.b64 {%0,%1}, %2;" : "=f"(r.x), "=f"(r.y) : "l"(v)); return r;
}
__device__ __forceinline__ float siluf(float x) { return x / (1.0f + expf(-x)); }

template <int KD>
__device__ __forceinline__ void dense64(const float* __restrict__ W,
                                        const float* in, float* out, float scale) {
#pragma unroll
    for (int t = 0; t < 2; t++) {
        u64 acc[16];
#pragma unroll
        for (int i = 0; i < 16; i++) acc[i] = 0ull;
#pragma unroll
        for (int k = 0; k < KD; k++) {
            u64 hk = pk2(in[k]);
            const ulonglong2* w = (const ulonglong2*)(W + k * 64 + t * 32);
#pragma unroll
            for (int p = 0; p < 8; p++) {
                ulonglong2 u = w[p];
                fma2(acc[2 * p], u.x, hk);
                fma2(acc[2 * p + 1], u.y, hk);
            }
        }
#pragma unroll
        for (int i = 0; i < 16; i++) {
            float2 f = upk(acc[i]);
            out[t * 32 + 2 * i]     = siluf(f.x * scale);
            out[t * 32 + 2 * i + 1] = siluf(f.y * scale);
        }
    }
}

// ---------------- mma / ldmatrix helpers ------------------------------------
__device__ __forceinline__ uint32_t smem_u32(const void* p) {
    uint32_t a;
    asm("{ .reg .u64 t; cvta.to.shared.u64 t, %1; cvt.u32.u64 %0, t; }"
        : "=r"(a) : "l"(p));
    return a;
}
__device__ __forceinline__ void ldm_x4(uint32_t* r, uint32_t addr) {
    asm volatile("ldmatrix.sync.aligned.m8n8.x4.shared.b16 {%0,%1,%2,%3}, [%4];"
                 : "=r"(r[0]), "=r"(r[1]), "=r"(r[2]), "=r"(r[3]) : "r"(addr));
}
__device__ __forceinline__ void mma_f16(float* d, const uint32_t* a,
                                        const uint32_t* b) {
    asm volatile(
        "mma.sync.aligned.m16n8k16.row.col.f32.f16.f16.f32 "
        "{%0,%1,%2,%3}, {%4,%5,%6,%7}, {%8,%9}, {%0,%1,%2,%3};"
        : "+f"(d[0]), "+f"(d[1]), "+f"(d[2]), "+f"(d[3])
        : "r"(a[0]), "r"(a[1]), "r"(a[2]), "r"(a[3]), "r"(b[0]), "r"(b[1]));
}

// ---------------- prep: counters + weight transposes + histogram -----------
__global__ void k_prep(const float* __restrict__ w1, const float* __restrict__ w2,
                       const float* __restrict__ w3,
                       const int* __restrict__ recv, int E, int N) {
    int i = blockIdx.x * blockDim.x + threadIdx.x;
    if (i < N) { g_cnt[i] = 0; g_cur[i] = 0; }
    if (i < MIXD * 64) {
        int n = i >> 6, k = i & 63;
        g_w3t[i] = __float2half_rn(w3[k * MIXD + n] * 0.125f);
    }
    if (i < 64 * 64) {
        int n = i >> 6, k = i & 63;
        g_w1t[i] = __float2half_rn(w1[k * 64 + n] * 0.125f);
        g_w2t[i] = __float2half_rn(w2[k * 64 + n] * 0.125f);
    }
}
__global__ void k_hist(const int* __restrict__ recv, int E) {
    int i = blockIdx.x * blockDim.x + threadIdx.x;
    if (i < E) atomicAdd(&g_cnt[recv[i]], 1);
}
__global__ void k_scan(int N) {
    __shared__ int wsum[32];
    int tid = threadIdx.x, lane = tid & 31, wid = tid >> 5;
    int per = (N + 1023) >> 10;
    int st = tid * per, en = min(st + per, N);
    int s = 0;
    for (int i = st; i < en; i++) s += g_cnt[i];
    int v = s;
#pragma unroll
    for (int o = 1; o < 32; o <<= 1) {
        int u = __shfl_up_sync(0xffffffffu, v, o);
        if (lane >= o) v += u;
    }
    if (lane == 31) wsum[wid] = v;
    __syncthreads();
    if (wid == 0) {
        int w = wsum[lane];
#pragma unroll
        for (int o = 1; o < 32; o <<= 1) {
            int u = __shfl_up_sync(0xffffffffu, w, o);
            if (lane >= o) w += u;
        }
        wsum[lane] = w;
    }
    __syncthreads();
    int base = (wid > 0 ? wsum[wid - 1] : 0) + (v - s);
    int run = base;
    for (int i = st; i < en; i++) { g_off[i] = run; run += g_cnt[i]; }
    if (tid == 1023) g_off[N] = run;
}
__global__ void k_scatter(const int* __restrict__ recv, int E) {
    int i = blockIdx.x * blockDim.x + threadIdx.x;
    if (i < E) {
        int r = recv[i];
        int p = atomicAdd(&g_cur[r], 1);
        g_csr[g_off[r] + p] = i;
    }
}

// ---------------- k_h0: geometry + layer0 -> fp16 ---------------------------
__global__ void __launch_bounds__(256) k_h0(
    const float* __restrict__ vectors, const float* __restrict__ radial,
    const float* __restrict__ w0, int E) {
    __shared__ float ws[512];
    int tid = threadIdx.x;
    {
        float4* d = (float4*)ws; const float4* s = (const float4*)w0;
        for (int i = tid; i < 128; i += 256) d[i] = s[i];
    }
    int e = blockIdx.x * 256 + tid;
    int ec = min(e, E - 1);
    bool valid = (e < E);

    {   // geometry
        float x = vectors[(size_t)ec * 3 + 0];
        float y = vectors[(size_t)ec * 3 + 1];
        float z = vectors[(size_t)ec * 3 + 2];
        float inv = rsqrtf(x * x + y * y + z * z);
        float r0 = x * inv, r1 = y * inv, r2 = z * inv;
        const float SQ3 = 1.7320508075688772f;
        if (valid) {
            float* G = g_geo + (size_t)e * 12;
            G[0] = r0; G[1] = r1; G[2] = r2;
            G[3] = SQ3 * (r0 * r0 - (1.f / 3.f));
            G[4] = SQ3 * r0 * r1;
            G[5] = SQ3 * r0 * r2;
            G[6] = SQ3 * r1 * r0;
            G[7] = SQ3 * (r1 * r1 - (1.f / 3.f));
            G[8] = SQ3 * r1 * r2;
            G[9] = SQ3 * r2 * r0;
            G[10] = SQ3 * r2 * r1;
            G[11] = SQ3 * (r2 * r2 - (1.f / 3.f));
        }
    }

    float rin[8];
    {
        const float4* rp = (const float4*)(radial + (size_t)ec * 8);
        float4 a4 = rp[0], b4 = rp[1];
        rin[0] = a4.x; rin[1] = a4.y; rin[2] = a4.z; rin[3] = a4.w;
        rin[4] = b4.x; rin[5] = b4.y; rin[6] = b4.z; rin[7] = b4.w;
    }
    __syncthreads();

    float h0[64];
    dense64<8>(ws, rin, h0, 0.35355339059327373f);

    uint32_t h2[32];
#pragma unroll
    for (int i = 0; i < 32; i++) {
        __half2 p = __floats2half2_rn(h0[2 * i], h0[2 * i + 1]);
        h2[i] = *(uint32_t*)&p;
    }
    uint4* dst = (uint4*)(g_h + (size_t)e * 64);
#pragma unroll
    for (int j = 0; j < 8; j++) dst[j] = ((uint4*)h2)[j];
}

// ---------------- k_l12: layers 1-2, single-pass fp16 HMMA, in-place --------
#define L_A 0
#define L_W 36864
#define L_TOTAL 46080

__global__ void __launch_bounds__(256, 4) k_l12(int E) {
    extern __shared__ char sm[];
    int tid = threadIdx.x;
    int w = tid >> 5, lane = tid & 31;
    int e0 = blockIdx.x * 256;
    int g = lane >> 3, r8 = lane & 7;
    int m_lane = lane >> 2, n_lane = (lane & 3) * 2;

    for (int idx = tid; idx < 2048; idx += 256) {
        int row = idx >> 3, seg = idx & 7;
        *(uint4*)(sm + L_A + row * 144 + seg * 16) =
            ((const uint4*)(g_h + (size_t)(e0 + row) * 64))[seg];
    }

    uint32_t Ab = smem_u32(sm + L_A);
    uint32_t Wb = smem_u32(sm + L_W);

#pragma unroll
    for (int L = 0; L < 2; L++) {
        const __half* wt = (L == 0) ? g_w1t : g_w2t;
        __syncthreads();
        for (int idx = tid; idx < 512; idx += 256) {
            int row = idx >> 3, seg = idx & 7;
            *(uint4*)(sm + L_W + row * 144 + seg * 16) =
                ((const uint4*)(wt + (size_t)row * 64))[seg];
        }
        __syncthreads();

#pragma unroll
        for (int mt = 0; mt < 2; mt++) {
            int rbase = 32 * w + 16 * mt;
            uint32_t aF[4][4];
#pragma unroll
            for (int kt = 0; kt < 4; kt++) {
                uint32_t off = (uint32_t)(rbase + (g & 1) * 8 + r8) * 144 +
                               kt * 32 + (g >> 1) * 16;
                ldm_x4(aF[kt], Ab + off);
            }
            uint32_t o[8][2];
#pragma unroll
            for (int nt = 0; nt < 8; nt++) {
                uint32_t bF[8];
#pragma unroll
                for (int p = 0; p < 2; p++) {
                    uint32_t off = (uint32_t)(nt * 8 + r8) * 144 + p * 64 + g * 16;
                    ldm_x4(&bF[p * 4], Wb + off);
                }
                float acc[4] = {0.f, 0.f, 0.f, 0.f};
#pragma unroll
                for (int kt = 0; kt < 4; kt++)
                    mma_f16(acc, aF[kt], &bF[kt * 2]);
#pragma unroll
                for (int half = 0; half < 2; half++) {
                    __half2 p = __floats2half2_rn(siluf(acc[half * 2]),
                                                  siluf(acc[half * 2 + 1]));
                    o[nt][half] = *(uint32_t*)&p;
                }
            }
#pragma unroll
            for (int nt = 0; nt < 8; nt++) {
                int col = nt * 8 + n_lane;
                if (L == 0) {
#pragma unroll
                    for (int half = 0; half < 2; half++) {
                        int row = rbase + m_lane + half * 8;
                        *(uint32_t*)(sm + L_A + row * 144 + col * 2) = o[nt][half];
                    }
                } else {
#pragma unroll
                    for (int half = 0; half < 2; half++) {
                        int row = rbase + m_lane + half * 8;
                        *(uint32_t*)(g_h + (size_t)(e0 + row) * 64 + col) =
                            o[nt][half];
                    }
                }
            }
        }
    }
}

// ---------------- k_gemm: mix = h @ w3^T, cc-split over 2 blocks/tile -------
#define GM_A 0
#define GM_B 36864
#define GM_TOTAL 48384

__global__ void __launch_bounds__(256, 4) k_gemm(int E) {
    extern __shared__ char sm[];
    int tid = threadIdx.x;
    int w = tid >> 5, lane = tid & 31;
    int e0 = (blockIdx.x >> 1) * 256;
    int cc0 = (blockIdx.x & 1) * 4;   // this block handles cc0..cc0+3

    for (int idx = tid; idx < 2048; idx += 256) {
        int row = idx >> 3, seg = idx & 7;
        *(uint4*)(sm + GM_A + row * 144 + seg * 16) =
            ((const uint4*)(g_h + (size_t)(e0 + row) * 64))[seg];
    }
    __syncthreads();

    uint32_t aF[2][4][4];
    {
        uint32_t Ab = smem_u32(sm + GM_A);
        int g = lane >> 3, r8 = lane & 7;
#pragma unroll
        for (int mt = 0; mt < 2; mt++) {
            int row = 32 * w + 16 * mt + (g & 1) * 8 + r8;
#pragma unroll
            for (int kt = 0; kt < 4; kt++)
                ldm_x4(aF[mt][kt], Ab + (uint32_t)row * 144 + kt * 32 + (g >> 1) * 16);
        }
    }
    __syncthreads();  // A region becomes the stage

    uint32_t Bb = smem_u32(sm + GM_B);
    int g = lane >> 3, r8 = lane & 7;
    int m_lane = lane >> 2, n_lane = (lane & 3) * 2;

    for (int ci = 0; ci < 4; ci++) {
        int cc = cc0 + ci;
        for (int idx = tid; idx < 640; idx += 256) {
            int rown = idx >> 3, seg = idx & 7;
            *(uint4*)(sm + GM_B + rown * 144 + seg * 16) =
                *((const uint4*)(g_w3t + (size_t)(cc * 80 + rown) * 64) + seg);
        }
        __syncthreads();

#pragma unroll
        for (int mt = 0; mt < 2; mt++) {
#pragma unroll
            for (int nt = 0; nt < 10; nt++) {
                uint32_t bF[8];
#pragma unroll
                for (int p = 0; p < 2; p++)
                    ldm_x4(&bF[p * 4],
                           Bb + (uint32_t)(nt * 8 + r8) * 144 + p * 64 + g * 16);
                float acc[4] = {0.f, 0.f, 0.f, 0.f};
#pragma unroll
                for (int kt = 0; kt < 4; kt++)
                    mma_f16(acc, aF[mt][kt], &bF[kt * 2]);
                int srow = w * 16 + m_lane;
                int cb = (nt * 8 + n_lane) * 2;
                *(__half2*)(sm + GM_A + srow * 176 + cb) =
                    __floats2half2_rn(acc[0], acc[1]);
                *(__half2*)(sm + GM_A + (srow + 8) * 176 + cb) =
                    __floats2half2_rn(acc[2], acc[3]);
            }
            __syncthreads();
            for (int idx = tid; idx < 2048; idx += 256) {
                int srow = idx >> 4, seg = idx & 15;
                int grow = e0 + 32 * (srow >> 4) + 16 * mt + (srow & 15);
                if (seg < 10 && grow < E)
                    *(uint4*)(g_mix + (size_t)grow * MIXD + cc * 80 + seg * 8) =
                        *(uint4*)(sm + GM_A + srow * 176 + seg * 16);
            }
            __syncthreads();
        }
    }
}

// ---------------- per-node gather (R10 champion config) ---------------------
#define CHUNK 64
__global__ void __launch_bounds__(256) k_node(
    const float* __restrict__ nf, const int* __restrict__ senders,
    float* __restrict__ out) {
    __shared__ int sE[CHUNK], sS[CHUNK];
    __shared__ float red[11 * 128];
    int n = blockIdx.x;
    int tid = threadIdx.x;
    int c = tid & 127, grp = tid >> 7;
    int beg = g_off[n], end = g_off[n + 1];

    float as0 = 0.f, as1 = 0.f;
    float av0 = 0.f, av1 = 0.f, av2 = 0.f;
    float aw0 = 0.f, aw1 = 0.f, aw2 = 0.f;
    float au0 = 0.f, au1 = 0.f, au2 = 0.f;

    for (int ch = beg; ch < end; ch += CHUNK) {
        int cnt = min(CHUNK, end - ch);
        __syncthreads();
        if (tid < cnt) {
            int e = g_csr[ch + tid];
            sE[tid] = e;
            sS[tid] = senders[e];
        }
        __syncthreads();
        for (int i = grp; i < cnt; i += 2) {
            int e = sE[i];
            int s = sS[i];
            const float* fr = nf + (size_t)s * 512;
            float ss = fr[c];
            float v0 = fr[128 + c * 3 + 0];
            float v1 = fr[128 + c * 3 + 1];
            float v2 = fr[128 + c * 3 + 2];
            const float4* G = (const float4*)(g_geo + (size_t)e * 12);
            float4 ga = G[0], gb = G[1], gc4 = G[2];
            const __half* mx = g_mix + (size_t)e * MIXD;
            float m0 = __half2float(mx[c]);
            float m1 = __half2float(mx[C + c]);
            float m2 = __half2float(mx[2 * C + c]);
            float m3 = __half2float(mx[3 * C + c]);
            float m4 = __half2float(mx[4 * C + c]);
            float r0 = ga.x, r1 = ga.y, r2 = ga.z;
            float y00 = ga.w, y01 = gb.x, y02 = gb.y, y11 = gb.w,
                  y12 = gc4.x, y22 = gc4.w;
            float tp0 = v0 * r0 + v1 * r1 + v2 * r2;
            as0 += ss * m0;
            as1 += tp0 * m1;
            av0 += v0 * m2; av1 += v1 * m2; av2 += v2 * m2;
            float sm3 = ss * m3;
            aw0 += sm3 * r0; aw1 += sm3 * r1; aw2 += sm3 * r2;
            float t0 = y00 * v0 + y01 * v1 + y02 * v2;
            float t1 = y01 * v0 + y11 * v1 + y12 * v2;
            float t2 = y02 * v0 + y12 * v1 + y22 * v2;
            au0 += t0 * m4; au1 += t1 * m4; au2 += t2 * m4;
        }
    }

    if (grp == 1) {
        red[c] = as0;            red[128 + c] = as1;
        red[256 + c] = av0;      red[384 + c] = av1;  red[512 + c] = av2;
        red[640 + c] = aw0;      red[768 + c] = aw1;  red[896 + c] = aw2;
        red[1024 + c] = au0;     red[1152 + c] = au1; red[1280 + c] = au2;
    }
    __syncthreads();
    if (grp == 0) {
        as0 += red[c];           as1 += red[128 + c];
        av0 += red[256 + c];     av1 += red[384 + c]; av2 += red[512 + c];
        aw0 += red[640 + c];     aw1 += red[768 + c]; aw2 += red[896 + c];
        au0 += red[1024 + c];    au1 += red[1152 + c]; au2 += red[1280 + c];
        const float sc = 0.31622776601683794f;  // 1/sqrt(10)
        float* ob = out + (size_t)n * 1408;
        ob[c] = as0 * sc;
        ob[C + c] = as1 * sc;
        ob[256 + c * 3 + 0] = av0 * sc;
        ob[256 + c * 3 + 1] = av1 * sc;
        ob[256 + c * 3 + 2] = av2 * sc;
        ob[640 + c * 3 + 0] = aw0 * sc;
        ob[640 + c * 3 + 1] = aw1 * sc;
        ob[640 + c * 3 + 2] = aw2 * sc;
        ob[1024 + c * 3 + 0] = au0 * sc;
        ob[1024 + c * 3 + 1] = au1 * sc;
        ob[1024 + c * 3 + 2] = au2 * sc;
    }
}

// ---------------- launch -----------------------------------------------------
extern "C" void kernel_launch(void* const* d_in, const int* in_sizes, int n_in,
                              void* d_out, int out_size) {
    const float* vectors    = (const float*)d_in[0];
    const float* node_feats = (const float*)d_in[1];
    const float* radial     = (const float*)d_in[2];
    const float* w0         = (const float*)d_in[3];
    const float* w1         = (const float*)d_in[4];
    const float* w2         = (const float*)d_in[5];
    const float* w3         = (const float*)d_in[6];
    const int*   senders    = (const int*)d_in[7];
    const int*   receivers  = (const int*)d_in[8];
    float* out = (float*)d_out;

    int E = in_sizes[0] / 3;
    int N = in_sizes[1] / 512;

    cudaFuncSetAttribute(k_gemm, cudaFuncAttributeMaxDynamicSharedMemorySize,
                         GM_TOTAL);
    cudaFuncSetAttribute(k_l12, cudaFuncAttributeMaxDynamicSharedMemorySize,
                         L_TOTAL);

    int nEB = (E + 255) / 256;
    k_prep<<<(MIXD * 64 + 255) / 256, 256>>>(w1, w2, w3, receivers, E, N);
    k_h0<<<nEB, 256>>>(vectors, radial, w0, E);
    k_hist<<<(E + 255) / 256, 256>>>(receivers, E);
    k_l12<<<nEB, 256, L_TOTAL>>>(E);
    k_scan<<<1, 1024>>>(N);
    k_scatter<<<(E + 255) / 256, 256>>>(receivers, E);
    k_gemm<<<nEB * 2, 256, GM_TOTAL>>>(E);
    k_node<<<N, 256>>>(node_feats, senders, out);
}

// round 16
// speedup vs baseline: 1.2734x; 1.0758x over previous
#include <cuda_runtime.h>
#include <cuda_bf16.h>
#include <cuda_fp16.h>
#include <math.h>
#include <stdint.h>

#define C 128
#define MIXD 640
#define E_MAX 100000
#define N_MAX 10000

typedef unsigned long long u64;

// ---------------- scratch (static device arrays: allocation-free) ----------
__device__ __align__(16) __half g_mix[(size_t)E_MAX * MIXD];
__device__ __align__(16) __half g_h[(size_t)(E_MAX + 256) * 64];  // h0 -> h2 in place
__device__ __align__(16) float  g_geo[(size_t)(E_MAX + 256) * 12];
__device__ __align__(16) __half g_w3t[MIXD * 64];   // w3^T/8 fp16
__device__ __align__(16) __half g_w1t[64 * 64];     // w1^T/8 fp16
__device__ __align__(16) __half g_w2t[64 * 64];     // w2^T/8 fp16
__device__ int g_cnt[N_MAX];
__device__ int g_cur[N_MAX];
__device__ int g_off[N_MAX + 1];
__device__ int g_csr[E_MAX];

// ---------------- f32x2 helpers --------------------------------------------
__device__ __forceinline__ u64 pk2(float x) {
    u64 r; asm("mov.b64 %0,{%1,%1};" : "=l"(r) : "f"(x)); return r;
}
__device__ __forceinline__ void fma2(u64& d, u64 a, u64 b) {
    asm("fma.rn.f32x2 %0, %1, %2, %0;" : "+l"(d) : "l"(a), "l"(b));
}
__device__ __forceinline__ float2 upk(u64 v) {
    float2 r; asm("mov.b64 {%0,%1}, %2;" : "=f"(r.x), "=f"(r.y) : "l"(v)); return r;
}
__device__ __forceinline__ float siluf(float x) { return x / (1.0f + expf(-x)); }

// ---------------- mma / ldmatrix helpers ------------------------------------
__device__ __forceinline__ uint32_t smem_u32(const void* p) {
    uint32_t a;
    asm("{ .reg .u64 t; cvta.to.shared.u64 t, %1; cvt.u32.u64 %0, t; }"
        : "=r"(a) : "l"(p));
    return a;
}
__device__ __forceinline__ void ldm_x4(uint32_t* r, uint32_t addr) {
    asm volatile("ldmatrix.sync.aligned.m8n8.x4.shared.b16 {%0,%1,%2,%3}, [%4];"
                 : "=r"(r[0]), "=r"(r[1]), "=r"(r[2]), "=r"(r[3]) : "r"(addr));
}
__device__ __forceinline__ void mma_f16(float* d, const uint32_t* a,
                                        const uint32_t* b) {
    asm volatile(
        "mma.sync.aligned.m16n8k16.row.col.f32.f16.f16.f32 "
        "{%0,%1,%2,%3}, {%4,%5,%6,%7}, {%8,%9}, {%0,%1,%2,%3};"
        : "+f"(d[0]), "+f"(d[1]), "+f"(d[2]), "+f"(d[3])
        : "r"(a[0]), "r"(a[1]), "r"(a[2]), "r"(a[3]), "r"(b[0]), "r"(b[1]));
}

// ---------------- prep: counters + weight transposes + histogram -----------
__global__ void k_prep(const float* __restrict__ w1, const float* __restrict__ w2,
                       const float* __restrict__ w3,
                       const int* __restrict__ recv, int E, int N) {
    int i = blockIdx.x * blockDim.x + threadIdx.x;
    if (i < N) { g_cnt[i] = 0; g_cur[i] = 0; }
    if (i < MIXD * 64) {
        int n = i >> 6, k = i & 63;
        g_w3t[i] = __float2half_rn(w3[k * MIXD + n] * 0.125f);
    }
    if (i < 64 * 64) {
        int n = i >> 6, k = i & 63;
        g_w1t[i] = __float2half_rn(w1[k * 64 + n] * 0.125f);
        g_w2t[i] = __float2half_rn(w2[k * 64 + n] * 0.125f);
    }
    // histogram (grid covers E; counters zeroed by earlier threads of same
    // launch would race, so use grid-stride barrier-free trick: counters for
    // node j are zeroed by thread j which runs in the same launch — instead
    // zero first via separate pass below)
}
__global__ void k_hist(const int* __restrict__ recv, int E) {
    int i = blockIdx.x * blockDim.x + threadIdx.x;
    if (i < E) atomicAdd(&g_cnt[recv[i]], 1);
}
__global__ void k_scan(int N) {
    __shared__ int wsum[32];
    int tid = threadIdx.x, lane = tid & 31, wid = tid >> 5;
    int per = (N + 1023) >> 10;
    int st = tid * per, en = min(st + per, N);
    int s = 0;
    for (int i = st; i < en; i++) s += g_cnt[i];
    int v = s;
#pragma unroll
    for (int o = 1; o < 32; o <<= 1) {
        int u = __shfl_up_sync(0xffffffffu, v, o);
        if (lane >= o) v += u;
    }
    if (lane == 31) wsum[wid] = v;
    __syncthreads();
    if (wid == 0) {
        int w = wsum[lane];
#pragma unroll
        for (int o = 1; o < 32; o <<= 1) {
            int u = __shfl_up_sync(0xffffffffu, w, o);
            if (lane >= o) w += u;
        }
        wsum[lane] = w;
    }
    __syncthreads();
    int base = (wid > 0 ? wsum[wid - 1] : 0) + (v - s);
    int run = base;
    for (int i = st; i < en; i++) { g_off[i] = run; run += g_cnt[i]; }
    if (tid == 1023) g_off[N] = run;
}
__global__ void k_scatter(const int* __restrict__ recv, int E) {
    int i = blockIdx.x * blockDim.x + threadIdx.x;
    if (i < E) {
        int r = recv[i];
        int p = atomicAdd(&g_cur[r], 1);
        g_csr[g_off[r] + p] = i;
    }
}

// ---------------- k_h0: geometry + layer0 -> fp16 (register-lean) -----------
__global__ void __launch_bounds__(256, 4) k_h0(
    const float* __restrict__ vectors, const float* __restrict__ radial,
    const float* __restrict__ w0, int E) {
    __shared__ float ws[512];
    int tid = threadIdx.x;
    {
        float4* d = (float4*)ws; const float4* s = (const float4*)w0;
        for (int i = tid; i < 128; i += 256) d[i] = s[i];
    }
    int e = blockIdx.x * 256 + tid;
    int ec = min(e, E - 1);
    bool valid = (e < E);

    {   // geometry
        float x = vectors[(size_t)ec * 3 + 0];
        float y = vectors[(size_t)ec * 3 + 1];
        float z = vectors[(size_t)ec * 3 + 2];
        float inv = rsqrtf(x * x + y * y + z * z);
        float r0 = x * inv, r1 = y * inv, r2 = z * inv;
        const float SQ3 = 1.7320508075688772f;
        if (valid) {
            float* G = g_geo + (size_t)e * 12;
            G[0] = r0; G[1] = r1; G[2] = r2;
            G[3] = SQ3 * (r0 * r0 - (1.f / 3.f));
            G[4] = SQ3 * r0 * r1;
            G[5] = SQ3 * r0 * r2;
            G[6] = SQ3 * r1 * r0;
            G[7] = SQ3 * (r1 * r1 - (1.f / 3.f));
            G[8] = SQ3 * r1 * r2;
            G[9] = SQ3 * r2 * r0;
            G[10] = SQ3 * r2 * r1;
            G[11] = SQ3 * (r2 * r2 - (1.f / 3.f));
        }
    }

    float rin[8];
    {
        const float4* rp = (const float4*)(radial + (size_t)ec * 8);
        float4 a4 = rp[0], b4 = rp[1];
        rin[0] = a4.x; rin[1] = a4.y; rin[2] = a4.z; rin[3] = a4.w;
        rin[4] = b4.x; rin[5] = b4.y; rin[6] = b4.z; rin[7] = b4.w;
    }
    __syncthreads();

    // layer0 in two 32-column halves; store each immediately (low reg pressure)
    const float scale = 0.35355339059327373f;  // 1/sqrt(8)
#pragma unroll
    for (int t = 0; t < 2; t++) {
        u64 acc[16];
#pragma unroll
        for (int i = 0; i < 16; i++) acc[i] = 0ull;
#pragma unroll
        for (int k = 0; k < 8; k++) {
            u64 hk = pk2(rin[k]);
            const ulonglong2* w = (const ulonglong2*)(ws + k * 64 + t * 32);
#pragma unroll
            for (int p = 0; p < 8; p++) {
                ulonglong2 u = w[p];
                fma2(acc[2 * p], u.x, hk);
                fma2(acc[2 * p + 1], u.y, hk);
            }
        }
        uint32_t h2[16];
#pragma unroll
        for (int i = 0; i < 16; i++) {
            float2 f = upk(acc[i]);
            __half2 p = __floats2half2_rn(siluf(f.x * scale), siluf(f.y * scale));
            h2[i] = *(uint32_t*)&p;
        }
        uint4* dst = (uint4*)(g_h + (size_t)e * 64 + t * 32);
#pragma unroll
        for (int j = 0; j < 4; j++) dst[j] = ((uint4*)h2)[j];
    }
}

// ---------------- k_l12: layers 1-2, single-pass fp16 HMMA, in-place --------
#define L_A 0
#define L_W 36864
#define L_TOTAL 46080

__global__ void __launch_bounds__(256, 4) k_l12(int E) {
    extern __shared__ char sm[];
    int tid = threadIdx.x;
    int w = tid >> 5, lane = tid & 31;
    int e0 = blockIdx.x * 256;
    int g = lane >> 3, r8 = lane & 7;
    int m_lane = lane >> 2, n_lane = (lane & 3) * 2;

    for (int idx = tid; idx < 2048; idx += 256) {
        int row = idx >> 3, seg = idx & 7;
        *(uint4*)(sm + L_A + row * 144 + seg * 16) =
            ((const uint4*)(g_h + (size_t)(e0 + row) * 64))[seg];
    }

    uint32_t Ab = smem_u32(sm + L_A);
    uint32_t Wb = smem_u32(sm + L_W);

#pragma unroll
    for (int L = 0; L < 2; L++) {
        const __half* wt = (L == 0) ? g_w1t : g_w2t;
        __syncthreads();
        for (int idx = tid; idx < 512; idx += 256) {
            int row = idx >> 3, seg = idx & 7;
            *(uint4*)(sm + L_W + row * 144 + seg * 16) =
                ((const uint4*)(wt + (size_t)row * 64))[seg];
        }
        __syncthreads();

#pragma unroll
        for (int mt = 0; mt < 2; mt++) {
            int rbase = 32 * w + 16 * mt;
            uint32_t aF[4][4];
#pragma unroll
            for (int kt = 0; kt < 4; kt++) {
                uint32_t off = (uint32_t)(rbase + (g & 1) * 8 + r8) * 144 +
                               kt * 32 + (g >> 1) * 16;
                ldm_x4(aF[kt], Ab + off);
            }
            uint32_t o[8][2];
#pragma unroll
            for (int nt = 0; nt < 8; nt++) {
                uint32_t bF[8];
#pragma unroll
                for (int p = 0; p < 2; p++) {
                    uint32_t off = (uint32_t)(nt * 8 + r8) * 144 + p * 64 + g * 16;
                    ldm_x4(&bF[p * 4], Wb + off);
                }
                float acc[4] = {0.f, 0.f, 0.f, 0.f};
#pragma unroll
                for (int kt = 0; kt < 4; kt++)
                    mma_f16(acc, aF[kt], &bF[kt * 2]);
#pragma unroll
                for (int half = 0; half < 2; half++) {
                    __half2 p = __floats2half2_rn(siluf(acc[half * 2]),
                                                  siluf(acc[half * 2 + 1]));
                    o[nt][half] = *(uint32_t*)&p;
                }
            }
#pragma unroll
            for (int nt = 0; nt < 8; nt++) {
                int col = nt * 8 + n_lane;
                if (L == 0) {
#pragma unroll
                    for (int half = 0; half < 2; half++) {
                        int row = rbase + m_lane + half * 8;
                        *(uint32_t*)(sm + L_A + row * 144 + col * 2) = o[nt][half];
                    }
                } else {
#pragma unroll
                    for (int half = 0; half < 2; half++) {
                        int row = rbase + m_lane + half * 8;
                        *(uint32_t*)(g_h + (size_t)(e0 + row) * 64 + col) =
                            o[nt][half];
                    }
                }
            }
        }
    }
}

// ---------------- k_gemm: mix = h @ w3^T via HMMA (R10 config) --------------
#define GM_A 0
#define GM_B 36864
#define GM_TOTAL 48384

__global__ void __launch_bounds__(256, 4) k_gemm(int E) {
    extern __shared__ char sm[];
    int tid = threadIdx.x;
    int w = tid >> 5, lane = tid & 31;
    int e0 = blockIdx.x * 256;

    for (int idx = tid; idx < 2048; idx += 256) {
        int row = idx >> 3, seg = idx & 7;
        *(uint4*)(sm + GM_A + row * 144 + seg * 16) =
            ((const uint4*)(g_h + (size_t)(e0 + row) * 64))[seg];
    }
    __syncthreads();

    uint32_t aF[2][4][4];
    {
        uint32_t Ab = smem_u32(sm + GM_A);
        int g = lane >> 3, r8 = lane & 7;
#pragma unroll
        for (int mt = 0; mt < 2; mt++) {
            int row = 32 * w + 16 * mt + (g & 1) * 8 + r8;
#pragma unroll
            for (int kt = 0; kt < 4; kt++)
                ldm_x4(aF[mt][kt], Ab + (uint32_t)row * 144 + kt * 32 + (g >> 1) * 16);
        }
    }
    __syncthreads();  // A region becomes the stage

    uint32_t Bb = smem_u32(sm + GM_B);
    int g = lane >> 3, r8 = lane & 7;
    int m_lane = lane >> 2, n_lane = (lane & 3) * 2;

    for (int cc = 0; cc < 8; cc++) {
        for (int idx = tid; idx < 640; idx += 256) {
            int rown = idx >> 3, seg = idx & 7;
            *(uint4*)(sm + GM_B + rown * 144 + seg * 16) =
                *((const uint4*)(g_w3t + (size_t)(cc * 80 + rown) * 64) + seg);
        }
        __syncthreads();

#pragma unroll
        for (int mt = 0; mt < 2; mt++) {
#pragma unroll
            for (int nt = 0; nt < 10; nt++) {
                uint32_t bF[8];
#pragma unroll
                for (int p = 0; p < 2; p++)
                    ldm_x4(&bF[p * 4],
                           Bb + (uint32_t)(nt * 8 + r8) * 144 + p * 64 + g * 16);
                float acc[4] = {0.f, 0.f, 0.f, 0.f};
#pragma unroll
                for (int kt = 0; kt < 4; kt++)
                    mma_f16(acc, aF[mt][kt], &bF[kt * 2]);
                int srow = w * 16 + m_lane;
                int cb = (nt * 8 + n_lane) * 2;
                *(__half2*)(sm + GM_A + srow * 176 + cb) =
                    __floats2half2_rn(acc[0], acc[1]);
                *(__half2*)(sm + GM_A + (srow + 8) * 176 + cb) =
                    __floats2half2_rn(acc[2], acc[3]);
            }
            __syncthreads();
            for (int idx = tid; idx < 2048; idx += 256) {
                int srow = idx >> 4, seg = idx & 15;
                int grow = e0 + 32 * (srow >> 4) + 16 * mt + (srow & 15);
                if (seg < 10 && grow < E)
                    *(uint4*)(g_mix + (size_t)grow * MIXD + cc * 80 + seg * 8) =
                        *(uint4*)(sm + GM_A + srow * 176 + seg * 16);
            }
            __syncthreads();
        }
    }
}

// ---------------- per-node gather (R10 champion config) ---------------------
#define CHUNK 64
__global__ void __launch_bounds__(256) k_node(
    const float* __restrict__ nf, const int* __restrict__ senders,
    float* __restrict__ out) {
    __shared__ int sE[CHUNK], sS[CHUNK];
    __shared__ float red[11 * 128];
    int n = blockIdx.x;
    int tid = threadIdx.x;
    int c = tid & 127, grp = tid >> 7;
    int beg = g_off[n], end = g_off[n + 1];

    float as0 = 0.f, as1 = 0.f;
    float av0 = 0.f, av1 = 0.f, av2 = 0.f;
    float aw0 = 0.f, aw1 = 0.f, aw2 = 0.f;
    float au0 = 0.f, au1 = 0.f, au2 = 0.f;

    for (int ch = beg; ch < end; ch += CHUNK) {
        int cnt = min(CHUNK, end - ch);
        __syncthreads();
        if (tid < cnt) {
            int e = g_csr[ch + tid];
            sE[tid] = e;
            sS[tid] = senders[e];
        }
        __syncthreads();
        for (int i = grp; i < cnt; i += 2) {
            int e = sE[i];
            int s = sS[i];
            const float* fr = nf + (size_t)s * 512;
            float ss = fr[c];
            float v0 = fr[128 + c * 3 + 0];
            float v1 = fr[128 + c * 3 + 1];
            float v2 = fr[128 + c * 3 + 2];
            const float4* G = (const float4*)(g_geo + (size_t)e * 12);
            float4 ga = G[0], gb = G[1], gc4 = G[2];
            const __half* mx = g_mix + (size_t)e * MIXD;
            float m0 = __half2float(mx[c]);
            float m1 = __half2float(mx[C + c]);
            float m2 = __half2float(mx[2 * C + c]);
            float m3 = __half2float(mx[3 * C + c]);
            float m4 = __half2float(mx[4 * C + c]);
            float r0 = ga.x, r1 = ga.y, r2 = ga.z;
            float y00 = ga.w, y01 = gb.x, y02 = gb.y, y11 = gb.w,
                  y12 = gc4.x, y22 = gc4.w;
            float tp0 = v0 * r0 + v1 * r1 + v2 * r2;
            as0 += ss * m0;
            as1 += tp0 * m1;
            av0 += v0 * m2; av1 += v1 * m2; av2 += v2 * m2;
            float sm3 = ss * m3;
            aw0 += sm3 * r0; aw1 += sm3 * r1; aw2 += sm3 * r2;
            float t0 = y00 * v0 + y01 * v1 + y02 * v2;
            float t1 = y01 * v0 + y11 * v1 + y12 * v2;
            float t2 = y02 * v0 + y12 * v1 + y22 * v2;
            au0 += t0 * m4; au1 += t1 * m4; au2 += t2 * m4;
        }
    }

    if (grp == 1) {
        red[c] = as0;            red[128 + c] = as1;
        red[256 + c] = av0;      red[384 + c] = av1;  red[512 + c] = av2;
        red[640 + c] = aw0;      red[768 + c] = aw1;  red[896 + c] = aw2;
        red[1024 + c] = au0;     red[1152 + c] = au1; red[1280 + c] = au2;
    }
    __syncthreads();
    if (grp == 0) {
        as0 += red[c];           as1 += red[128 + c];
        av0 += red[256 + c];     av1 += red[384 + c]; av2 += red[512 + c];
        aw0 += red[640 + c];     aw1 += red[768 + c]; aw2 += red[896 + c];
        au0 += red[1024 + c];    au1 += red[1152 + c]; au2 += red[1280 + c];
        const float sc = 0.31622776601683794f;  // 1/sqrt(10)
        float* ob = out + (size_t)n * 1408;
        ob[c] = as0 * sc;
        ob[C + c] = as1 * sc;
        ob[256 + c * 3 + 0] = av0 * sc;
        ob[256 + c * 3 + 1] = av1 * sc;
        ob[256 + c * 3 + 2] = av2 * sc;
        ob[640 + c * 3 + 0] = aw0 * sc;
        ob[640 + c * 3 + 1] = aw1 * sc;
        ob[640 + c * 3 + 2] = aw2 * sc;
        ob[1024 + c * 3 + 0] = au0 * sc;
        ob[1024 + c * 3 + 1] = au1 * sc;
        ob[1024 + c * 3 + 2] = au2 * sc;
    }
}

// ---------------- launch -----------------------------------------------------
extern "C" void kernel_launch(void* const* d_in, const int* in_sizes, int n_in,
                              void* d_out, int out_size) {
    const float* vectors    = (const float*)d_in[0];
    const float* node_feats = (const float*)d_in[1];
    const float* radial     = (const float*)d_in[2];
    const float* w0         = (const float*)d_in[3];
    const float* w1         = (const float*)d_in[4];
    const float* w2         = (const float*)d_in[5];
    const float* w3         = (const float*)d_in[6];
    const int*   senders    = (const int*)d_in[7];
    const int*   receivers  = (const int*)d_in[8];
    float* out = (float*)d_out;

    int E = in_sizes[0] / 3;
    int N = in_sizes[1] / 512;

    cudaFuncSetAttribute(k_gemm, cudaFuncAttributeMaxDynamicSharedMemorySize,
                         GM_TOTAL);
    cudaFuncSetAttribute(k_l12, cudaFuncAttributeMaxDynamicSharedMemorySize,
                         L_TOTAL);

    int nEB = (E + 255) / 256;
    k_prep<<<(MIXD * 64 + 255) / 256, 256>>>(w1, w2, w3, receivers, E, N);
    k_h0<<<nEB, 256>>>(vectors, radial, w0, E);
    k_hist<<<(E + 255) / 256, 256>>>(receivers, E);
    k_l12<<<nEB, 256, L_TOTAL>>>(E);
    k_scan<<<1, 1024>>>(N);
    k_scatter<<<(E + 255) / 256, 256>>>(receivers, E);
    k_gemm<<<nEB, 256, GM_TOTAL>>>(E);
    k_node<<<N, 256>>>(node_feats, senders, out);
}